// round 1
// baseline (speedup 1.0000x reference)
#include <cuda_runtime.h>
#include <math.h>

// Problem constants
#define BB 32
#define SS 52
#define AA 5
#define CC 80
#define TT 50
#define PD (AA * (5 + CC))   // 425
#define NCELLS (BB * AA * SS * SS)   // 432,640
#define NROWS  (BB * SS * SS)        // 86,528

// Anchors (w, h)
__device__ __constant__ float c_anchors[AA * 2] = {
    1.3221f, 1.73145f,
    3.19275f, 4.00944f,
    5.05587f, 8.09892f,
    9.47112f, 4.84053f,
    11.2364f, 10.0071f
};

// Scratch: owner[cell] = (winning target index + 1), 0 = free.
// Zero-initialized at load; target kernel resets its touched cells to 0 at the
// end of every launch, so it is always all-zero at kernel entry (graph-safe).
__device__ int    g_owner[NCELLS];
__device__ double g_acc[3];   // [0]=coord raw, [1]=obj, [2]=sum conf^2 (all cells, obj cells pre-subtracted)

__device__ __forceinline__ float sigmoidf_(float x) {
    return 1.0f / (1.0f + expf(-x));
}

__device__ __forceinline__ float warp_sum(float v) {
    #pragma unroll
    for (int o = 16; o > 0; o >>= 1) v += __shfl_down_sync(0xFFFFFFFFu, v, o);
    return v;
}

// Compute best anchor + cell for one target. Returns cell index, fills decode info.
__device__ __forceinline__ void target_cell(const float* __restrict__ tgt, int b, int t,
                                            int& best_a, int& gi, int& gj,
                                            float& gx, float& gy, float& gtw, float& gth) {
    const float* tr = tgt + ((size_t)b * TT + t) * 5;
    gx = tr[0]; gy = tr[1];
    gtw = tr[2] * (float)SS;
    gth = tr[3] * (float)SS;
    float best = -1.0f;
    best_a = 0;
    #pragma unroll
    for (int a = 0; a < AA; a++) {
        float aw = c_anchors[a * 2], ah = c_anchors[a * 2 + 1];
        float inter = fminf(gtw, aw) * fminf(gth, ah);
        float uni = gtw * gth + aw * ah - inter;
        float iou = (uni > 0.0f) ? (inter / uni) : 0.0f;
        if (iou > best) { best = iou; best_a = a; }   // first max wins (strict >)
    }
    gi = (int)(gx * (float)SS);   // truncation == floor for positives
    gj = (int)(gy * (float)SS);
}

// K1: single block. Phase 0: zero accumulators. Phase 1: last-wins scatter.
// Phase 2: winners compute coord/obj losses and subtract their cell's conf^2.
// Phase 3: reset owner cells to 0 (self-cleaning scratch).
__global__ void k_targets(const float* __restrict__ pred, const float* __restrict__ tgt) {
    const int tid = threadIdx.x;
    const int nthreads = blockDim.x;

    if (tid < 3) g_acc[tid] = 0.0;
    __syncthreads();

    // Phase 1: scatter (last target wins => atomicMax on t+1)
    for (int n = tid; n < BB * TT; n += nthreads) {
        int b = n / TT, t = n % TT;
        int best_a, gi, gj; float gx, gy, gtw, gth;
        target_cell(tgt, b, t, best_a, gi, gj, gx, gy, gtw, gth);
        int cell = ((b * AA + best_a) * SS + gj) * SS + gi;
        atomicMax(&g_owner[cell], t + 1);
    }
    __syncthreads();

    // Phase 2: winners accumulate
    float l_coord = 0.0f, l_obj = 0.0f, l_sub = 0.0f;
    for (int n = tid; n < BB * TT; n += nthreads) {
        int b = n / TT, t = n % TT;
        int best_a, gi, gj; float gx, gy, gtw, gth;
        target_cell(tgt, b, t, best_a, gi, gj, gx, gy, gtw, gth);
        int cell = ((b * AA + best_a) * SS + gj) * SS + gi;
        if (g_owner[cell] != t + 1) continue;   // lost a collision

        const float* p = pred + (((size_t)b * SS + gj) * SS + gi) * PD + best_a * (5 + CC);
        float tx = p[0], ty = p[1], tw = p[2], th = p[3], score = p[4];
        float pbx = sigmoidf_(tx);
        float pby = sigmoidf_(ty);
        float pbw = expf(tw) * c_anchors[best_a * 2];
        float pbh = expf(th) * c_anchors[best_a * 2 + 1];
        float conf = sigmoidf_(score);

        float ggx = gx * (float)SS - (float)gi;
        float ggy = gy * (float)SS - (float)gj;

        // IoU of (ggx+gi, ggy+gj, gtw, gth) vs (pbx+gi, pby+gj, pbw, pbh)
        float cx1 = ggx + (float)gi, cy1 = ggy + (float)gj;
        float cx2 = pbx + (float)gi, cy2 = pby + (float)gj;
        float ix = fmaxf(0.0f, fminf(cx1 + gtw * 0.5f, cx2 + pbw * 0.5f)
                             - fmaxf(cx1 - gtw * 0.5f, cx2 - pbw * 0.5f));
        float iy = fmaxf(0.0f, fminf(cy1 + gth * 0.5f, cy2 + pbh * 0.5f)
                             - fmaxf(cy1 - gth * 0.5f, cy2 - pbh * 0.5f));
        float inter = ix * iy;
        float uni = gtw * gth + pbw * pbh - inter;
        float iou = (uni > 0.0f) ? (inter / uni) : 0.0f;

        const float eps = 1e-6f;
        float d1 = pbx - ggx, d2 = pby - ggy;
        float s1 = sqrtf(pbw + eps) - sqrtf(gtw + eps);
        float s2 = sqrtf(pbh + eps) - sqrtf(gth + eps);
        l_coord += d1 * d1 + d2 * d2 + s1 * s1 + s2 * s2;
        float od = iou - conf;
        l_obj += od * od;
        l_sub += conf * conf;   // this cell is NOT a no-obj cell
    }

    float wc = warp_sum(l_coord);
    float wo = warp_sum(l_obj);
    float ws = warp_sum(l_sub);
    if ((tid & 31) == 0) {
        if (wc != 0.0f) atomicAdd(&g_acc[0], (double)wc);
        if (wo != 0.0f) atomicAdd(&g_acc[1], (double)wo);
        if (ws != 0.0f) atomicAdd(&g_acc[2], (double)(-ws));
    }
    __syncthreads();

    // Phase 3: reset scratch (all writers write 0 — race-free)
    for (int n = tid; n < BB * TT; n += nthreads) {
        int b = n / TT, t = n % TT;
        int best_a, gi, gj; float gx, gy, gtw, gth;
        target_cell(tgt, b, t, best_a, gi, gj, gx, gy, gtw, gth);
        int cell = ((b * AA + best_a) * SS + gj) * SS + gi;
        g_owner[cell] = 0;
    }
}

// K2: streaming sum of conf^2 over ALL cells (obj cells already subtracted in K1).
// One thread per (b, j, i) row; reads the 5 anchor objectness scores.
__global__ void k_noobj(const float* __restrict__ pred) {
    int r = blockIdx.x * blockDim.x + threadIdx.x;
    float local = 0.0f;
    if (r < NROWS) {
        const float* row = pred + (size_t)r * PD;
        #pragma unroll
        for (int a = 0; a < AA; a++) {
            float conf = sigmoidf_(row[a * (5 + CC) + 4]);
            local += conf * conf;
        }
    }
    float w = warp_sum(local);
    if ((threadIdx.x & 31) == 0 && w != 0.0f) atomicAdd(&g_acc[2], (double)w);
}

// K3: finalize
__global__ void k_final(float* __restrict__ out, int out_size) {
    double coord_raw = g_acc[0];
    double obj       = g_acc[1];
    double noobj_raw = g_acc[2];
    double loss_coord = 5.0 * coord_raw;       // loss_coord_offset + loss_coord_scale (with lambda)
    double loss_noobj = 0.5 * noobj_raw;       // LAMBDA_NOOBJ * sum
    double total = 5.0 * loss_coord + obj + 0.5 * loss_noobj;
    if (out_size > 0) out[0] = (float)total;
    if (out_size > 1) out[1] = (float)loss_coord;
    if (out_size > 2) out[2] = (float)(obj + loss_noobj);
}

extern "C" void kernel_launch(void* const* d_in, const int* in_sizes, int n_in,
                              void* d_out, int out_size) {
    const float* pred = (const float*)d_in[0];   // [32,52,52,425]
    const float* tgt  = (const float*)d_in[1];   // [32,50,5]
    float* out = (float*)d_out;

    k_targets<<<1, 512>>>(pred, tgt);
    int nb = (NROWS + 255) / 256;                 // 338 blocks exactly covers 86,528
    k_noobj<<<nb, 256>>>(pred);
    k_final<<<1, 1>>>(out, out_size);
}